// round 9
// baseline (speedup 1.0000x reference)
#include <cuda_runtime.h>
#include <cuda_bf16.h>
#include <math.h>

// Problem constants
#define BB 64
#define TT 256
#define HH 512
#define LL 64
#define VV 500
#define SS 3
#define NEG_INF -1000000000.0f
#define EPS_C 1e-17f

// Output section offsets (float32 elements)
#define BTH (64UL*256UL*512UL)                 // 8,388,608
#define OFF_ENCS  0UL
#define OFF_RECS  25165824UL                   // 3*BTH
#define OFF_MASKS 49741824UL                   // + 3*64*256*500
#define OFF_LOGB  49774592UL                   // + 2*16384
#define OFF_SB    49807360UL                   // + 2*16384
#define OFF_LZ    49856512UL                   // + 3*16384
#define OFF_SZ    49881088UL                   // + 3*8192

#define NBLK 128
#define NTHR 128
#define HS_STRIDE 516                          // padded row stride (floats)
#define SMEM_FLOATS (64*HS_STRIDE + 4*256*8)   // 33024 + 8192 = 41216
#define SMEM_BYTES  (SMEM_FLOATS*4)            // 164864

// -------- device scratch (no allocation allowed) --------
__device__ float g_embW[500*2048];         // embed @ Wx
__device__ float g_embWpack[500*512*4];    // [a][j][i,f,g,o] (+bias folded)
__device__ float g_Wpack2[512*256*8];      // [j][k2][i0,i1,f0,f1,g0,g1,o0,o1]
__device__ float g_hA[64*512];
__device__ float g_hB[64*512];
__device__ float g_maskbuf[64*256];
__device__ float g_logacc[64*256];
__device__ float g_hid[16384*512];
__device__ float g_ro[64*512];
__device__ float g_hz[64*512];
__device__ float g_sz[64*64];
__device__ float g_hd[64*512];
__device__ float g_pred[64*500];

__device__ volatile unsigned g_bar_flag;
__device__ unsigned g_bar_count;

// ---------------- f32x2 packed FMA ----------------
__device__ __forceinline__ void ffma2(unsigned long long& d,
                                      unsigned long long a,
                                      unsigned long long b) {
    asm("fma.rn.f32x2 %0, %1, %2, %0;" : "+l"(d) : "l"(a), "l"(b));
}
__device__ __forceinline__ float lo32(unsigned long long v) {
    return __uint_as_float((unsigned)v);
}
__device__ __forceinline__ float hi32(unsigned long long v) {
    return __uint_as_float((unsigned)(v >> 32));
}
__device__ __forceinline__ float sigf(float x) { return 1.f / (1.f + expf(-x)); }

struct ull2 { unsigned long long x, y; };

// grid-wide spin barrier (128 co-resident blocks, 1 block/SM)
__device__ __forceinline__ void grid_barrier(unsigned& barBase) {
    __threadfence();
    __syncthreads();
    if (threadIdx.x == 0) {
        barBase++;
        unsigned old = atomicAdd(&g_bar_count, 1);
        if (old == NBLK - 1) {
            g_bar_count = 0;
            __threadfence();
            g_bar_flag = barBase;
        } else {
            while ((int)(g_bar_flag - barBase) < 0) { __nanosleep(32); }
        }
        __threadfence();
    }
    __syncthreads();
}

// ---------------- persistent masked-LSTM segment kernel ----------------
// 128 blocks x 128 threads. block -> 4 j columns; warp -> one j; lane -> b and b+32.
__global__ __launch_bounds__(NTHR, 1) void lstm_seg_k(
    const int* __restrict__ actions,
    const float* __restrict__ maskp,   // nullptr for seg 0
    float* __restrict__ enc)
{
    extern __shared__ float smem[];
    float* hs = smem;                    // [64][HS_STRIDE]
    float* ws = smem + 64*HS_STRIDE;     // [4][256][8]

    const int tid  = threadIdx.x;
    const int lane = tid & 31;
    const int jj   = tid >> 5;           // warp = j within block
    const int j    = blockIdx.x * 4 + jj;
    const int b1   = lane;
    const int b2   = lane + 32;

    // stage this block's Wh pack (constant across all steps)
    {
        const float4* src = (const float4*)(g_Wpack2 + (size_t)blockIdx.x * 8192);
        float4* dst = (float4*)ws;
#pragma unroll
        for (int i = tid; i < 2048; i += NTHR) dst[i] = src[i];
    }

    // init h ping buffer to zero (this thread's slots)
    g_hA[b1*HH + j] = 0.f;
    g_hA[b2*HH + j] = 0.f;

    float c1 = 0.f, c2 = 0.f;
    unsigned barBase = g_bar_flag;       // consistent across blocks at entry
    grid_barrier(barBase);               // h zeroed everywhere

    const float* wj = ws + jj * 2048;
    const float* hp1 = hs + b1 * HS_STRIDE;
    const float* hp2 = hs + b2 * HS_STRIDE;
    const int useMask = (maskp != nullptr);

    for (int t = 0; t < TT; t++) {
        const float* cur = (t & 1) ? g_hB : g_hA;
        float*       nxt = (t & 1) ? g_hA : g_hB;

        // stage h -> smem (coalesced loads, conflict-free STS.128)
        {
            const float4* src = (const float4*)cur;
#pragma unroll 8
            for (int f = tid; f < 8192; f += NTHR) {
                int r  = f >> 7;
                int c4 = f & 127;
                *(float4*)(hs + r * HS_STRIDE + c4 * 4) = src[f];
            }
        }
        __syncthreads();

        unsigned long long a0 = 0, a1 = 0, a2 = 0, a3 = 0;   // b1: i f g o
        unsigned long long a4 = 0, a5 = 0, a6 = 0, a7 = 0;   // b2: i f g o

#pragma unroll 4
        for (int k4 = 0; k4 < 128; k4++) {
            ull2 ha = *(const ull2*)(hp1 + 4 * k4);
            ull2 hb = *(const ull2*)(hp2 + 4 * k4);
            const float* wk = wj + k4 * 16;
            ull2 wA = *(const ull2*)(wk);        // i,f @k2
            ull2 wB = *(const ull2*)(wk + 4);    // g,o @k2
            ull2 wC = *(const ull2*)(wk + 8);    // i,f @k2+1
            ull2 wD = *(const ull2*)(wk + 12);   // g,o @k2+1

            ffma2(a0, ha.x, wA.x); ffma2(a1, ha.x, wA.y);
            ffma2(a2, ha.x, wB.x); ffma2(a3, ha.x, wB.y);
            ffma2(a0, ha.y, wC.x); ffma2(a1, ha.y, wC.y);
            ffma2(a2, ha.y, wD.x); ffma2(a3, ha.y, wD.y);

            ffma2(a4, hb.x, wA.x); ffma2(a5, hb.x, wA.y);
            ffma2(a6, hb.x, wB.x); ffma2(a7, hb.x, wB.y);
            ffma2(a4, hb.y, wC.x); ffma2(a5, hb.y, wC.y);
            ffma2(a6, hb.y, wD.x); ffma2(a7, hb.y, wD.y);
        }

        int act1 = actions[b1*TT + t];
        int act2 = actions[b2*TT + t];
        float4 x1 = *(const float4*)(g_embWpack + ((size_t)act1 * 512 + j) * 4);
        float4 x2 = *(const float4*)(g_embWpack + ((size_t)act2 * 512 + j) * 4);

        float zi1 = lo32(a0) + hi32(a0) + x1.x;
        float zf1 = lo32(a1) + hi32(a1) + x1.y;
        float zg1 = lo32(a2) + hi32(a2) + x1.z;
        float zo1 = lo32(a3) + hi32(a3) + x1.w;
        float zi2 = lo32(a4) + hi32(a4) + x2.x;
        float zf2 = lo32(a5) + hi32(a5) + x2.y;
        float zg2 = lo32(a6) + hi32(a6) + x2.z;
        float zo2 = lo32(a7) + hi32(a7) + x2.w;

        float c1n = sigf(zf1) * c1 + sigf(zi1) * tanhf(zg1);
        float h1n = sigf(zo1) * tanhf(c1n);
        float c2n = sigf(zf2) * c2 + sigf(zi2) * tanhf(zg2);
        float h2n = sigf(zo2) * tanhf(c2n);

        enc[((size_t)b1*TT + t)*HH + j] = h1n;
        enc[((size_t)b2*TT + t)*HH + j] = h2n;

        float m1 = useMask ? maskp[b1*TT + t] : 1.f;
        float m2 = useMask ? maskp[b2*TT + t] : 1.f;
        c1 = m1 * c1n;
        c2 = m2 * c2n;
        nxt[b1*HH + j] = m1 * h1n;
        nxt[b2*HH + j] = m2 * h2n;

        if (t < TT - 1) grid_barrier(barBase);
        else __syncthreads();
    }
}

// ---------------- pack kernels ----------------
__global__ void pack_embW_k(const float* __restrict__ b_lstm) {
    int a = blockIdx.x;         // 0..499
    int j = threadIdx.x;        // 0..511
    float4 v;
    v.x = g_embW[(size_t)a*2048 +        j] + b_lstm[j];
    v.y = g_embW[(size_t)a*2048 +  512 + j] + b_lstm[512 + j];
    v.z = g_embW[(size_t)a*2048 + 1024 + j] + b_lstm[1024 + j];
    v.w = g_embW[(size_t)a*2048 + 1536 + j] + b_lstm[1536 + j];
    *(float4*)(g_embWpack + ((size_t)a*512 + j)*4) = v;
}

// pack Wh into [j][k2][i0,i1,f0,f1,g0,g1,o0,o1]
__global__ void pack_Wh2_k(const float* __restrict__ Wh) {
    int idx = blockIdx.x * blockDim.x + threadIdx.x;   // 131072
    if (idx >= 512*256) return;
    int j  = idx >> 8;
    int k2 = idx & 255;
    float v[8];
#pragma unroll
    for (int g = 0; g < 4; g++) {
#pragma unroll
        for (int p = 0; p < 2; p++)
            v[g*2 + p] = Wh[(size_t)(2*k2 + p)*2048 + g*512 + j];
    }
    float4* dst = (float4*)(g_Wpack2 + ((size_t)j*256 + k2)*8);
    dst[0] = make_float4(v[0], v[1], v[2], v[3]);
    dst[1] = make_float4(v[4], v[5], v[6], v[7]);
}

// ---------------- generic tiled SGEMM ----------------
#define BM 64
#define BN 64
#define BKT 32
__global__ __launch_bounds__(256) void sgemm_k(
    const float* __restrict__ A, int lda,
    const float* __restrict__ B, int ldb,
    float* __restrict__ C, int ldc,
    int M, int N, int K,
    const float* __restrict__ bias, int relu)
{
    __shared__ float As[BKT][BM + 1];
    __shared__ float Bs[BKT][BN];

    int m0 = blockIdx.y * BM;
    int n0 = blockIdx.x * BN;
    int tid = threadIdx.x;
    int tx = tid & 15;
    int ty = tid >> 4;

    float acc[4][4];
#pragma unroll
    for (int i = 0; i < 4; i++)
#pragma unroll
        for (int jq = 0; jq < 4; jq++) acc[i][jq] = 0.f;

    for (int k0 = 0; k0 < K; k0 += BKT) {
#pragma unroll
        for (int i = 0; i < (BM*BKT)/256; i++) {
            int idx = tid + i*256;
            int m  = idx >> 5;
            int kk = idx & 31;
            int gm = m0 + m;
            As[kk][m] = (gm < M) ? A[(size_t)gm*lda + k0 + kk] : 0.f;
        }
#pragma unroll
        for (int i = 0; i < (BKT*BN)/256; i++) {
            int idx = tid + i*256;
            int kk = idx >> 6;
            int n  = idx & 63;
            int gn = n0 + n;
            Bs[kk][n] = (gn < N) ? B[(size_t)(k0+kk)*ldb + gn] : 0.f;
        }
        __syncthreads();
#pragma unroll
        for (int kk = 0; kk < BKT; kk++) {
            float a0 = As[kk][ty*4+0];
            float a1 = As[kk][ty*4+1];
            float a2 = As[kk][ty*4+2];
            float a3 = As[kk][ty*4+3];
            float4 b4 = *(const float4*)&Bs[kk][tx*4];
            acc[0][0] += a0*b4.x; acc[0][1] += a0*b4.y; acc[0][2] += a0*b4.z; acc[0][3] += a0*b4.w;
            acc[1][0] += a1*b4.x; acc[1][1] += a1*b4.y; acc[1][2] += a1*b4.z; acc[1][3] += a1*b4.w;
            acc[2][0] += a2*b4.x; acc[2][1] += a2*b4.y; acc[2][2] += a2*b4.z; acc[2][3] += a2*b4.w;
            acc[3][0] += a3*b4.x; acc[3][1] += a3*b4.y; acc[3][2] += a3*b4.z; acc[3][3] += a3*b4.w;
        }
        __syncthreads();
    }

#pragma unroll
    for (int i = 0; i < 4; i++) {
        int gm = m0 + ty*4 + i;
        if (gm >= M) continue;
#pragma unroll
        for (int jq = 0; jq < 4; jq++) {
            int gn = n0 + tx*4 + jq;
            if (gn >= N) continue;
            float v = acc[i][jq];
            if (bias) v += bias[gn];
            if (relu) v = fmaxf(v, 0.f);
            C[(size_t)gm*ldc + gn] = v;
        }
    }
}

// ---------------- small helpers ----------------
__global__ void zero1_k(float* a, int n) {
    int i = blockIdx.x * blockDim.x + threadIdx.x;
    if (i < n) a[i] = 0.f;
}

__global__ __launch_bounds__(256) void rowdot_k(
    const float* __restrict__ hid, const float* __restrict__ Wb2,
    const float* __restrict__ bb2, float* __restrict__ logits_out)
{
    int row  = blockIdx.x * 8 + (threadIdx.x >> 5);
    int lane = threadIdx.x & 31;
    const float* hr = hid + (size_t)row * 512;
    float acc = 0.f;
#pragma unroll
    for (int i = lane; i < 512; i += 32) acc += hr[i] * Wb2[i];
#pragma unroll
    for (int o = 16; o > 0; o >>= 1) acc += __shfl_down_sync(0xffffffffu, acc, o);
    if (lane == 0) {
        float v = acc + bb2[0];
        if ((row & 255) == 0) v = NEG_INF;
        logits_out[row] = v;
    }
}

__global__ __launch_bounds__(256) void softmax_mask_k(
    const float* __restrict__ logits, const float* __restrict__ gumbel,
    float* __restrict__ sb_out, float* __restrict__ mask_out,
    float* __restrict__ maskbuf, float* __restrict__ logacc)
{
    int b = blockIdx.x;
    int t = threadIdx.x;
    __shared__ float sh[256];

    float x = logits[b*TT + t] + gumbel[b*TT + t];
    sh[t] = x; __syncthreads();
    for (int s = 128; s > 0; s >>= 1) { if (t < s) sh[t] = fmaxf(sh[t], sh[t+s]); __syncthreads(); }
    float mx = sh[0]; __syncthreads();

    float e = expf(x - mx);
    sh[t] = e; __syncthreads();
    for (int s = 128; s > 0; s >>= 1) { if (t < s) sh[t] += sh[t+s]; __syncthreads(); }
    float sum = sh[0]; __syncthreads();

    float p = e / sum;
    sb_out[b*TT + t] = p;

    sh[t] = p; __syncthreads();
    for (int off = 1; off < 256; off <<= 1) {
        float v = (t >= off) ? sh[t - off] : 0.f;
        __syncthreads();
        sh[t] += v;
        __syncthreads();
    }
    float cum = sh[t];
    float la = logacc[b*TT + t] + logf(cum + EPS_C);
    logacc[b*TT + t] = la;
    float m = expf(la);
    maskbuf[b*TT + t] = m;
    mask_out[b*TT + t] = m;
}

__global__ void onehot_k(const int* __restrict__ lengths, float* __restrict__ sb_out) {
    int b = blockIdx.x, t = threadIdx.x;
    sb_out[b*TT + t] = (t == lengths[b] - 1) ? 1.f : 0.f;
}

__global__ __launch_bounds__(512) void readout_k(
    const float* __restrict__ enc, const float* __restrict__ sb,
    float* __restrict__ ro)
{
    int b = blockIdx.x;
    int h = threadIdx.x;
    __shared__ float s_sb[256];
    if (h < 256) s_sb[h] = sb[b*TT + h];
    __syncthreads();
    const float* e = enc + (size_t)b*TT*HH;
    float acc = 0.f;
    for (int t = 0; t < TT - 1; t++)
        acc += e[(size_t)t*HH + h] * s_sb[t + 1];
    ro[b*HH + h] = acc;
}

__global__ void samplez_k(const float* __restrict__ lz, const float* __restrict__ eps,
                          float* __restrict__ sz_out, float* __restrict__ szbuf)
{
    int id = blockIdx.x * blockDim.x + threadIdx.x;
    int b = id >> 6, l = id & 63;
    float mu = lz[b*128 + l];
    float lv = lz[b*128 + 64 + l];
    float v = mu + expf(0.5f * lv) * eps[b*64 + l];
    sz_out[id] = v;
    szbuf[id]  = v;
}

__global__ __launch_bounds__(256) void recs_k(const float* __restrict__ pred,
                                              float* __restrict__ out)
{
    long idx = (long)blockIdx.x * 256 + threadIdx.x;
    if (idx >= (long)BB*TT*VV) return;
    int v = (int)(idx % VV);
    int b = (int)(idx / ((long)VV * TT));
    out[idx] = pred[b*VV + v];
}

// ---------------- host orchestration ----------------
extern "C" void kernel_launch(void* const* d_in, const int* in_sizes, int n_in,
                              void* d_out, int out_size)
{
    const int*   actions = (const int*)  d_in[0];
    const int*   lengths = (const int*)  d_in[1];
    const float* gumbel  = (const float*)d_in[2];
    const float* eps_z   = (const float*)d_in[3];
    const float* embed   = (const float*)d_in[4];
    const float* Wx      = (const float*)d_in[5];
    const float* Wh      = (const float*)d_in[6];
    const float* b_lstm  = (const float*)d_in[7];
    const float* Wz1     = (const float*)d_in[8];
    const float* bz1     = (const float*)d_in[9];
    const float* Wz2     = (const float*)d_in[10];
    const float* bz2     = (const float*)d_in[11];
    const float* Wb1     = (const float*)d_in[12];
    const float* bb1     = (const float*)d_in[13];
    const float* Wb2     = (const float*)d_in[14];
    const float* bb2     = (const float*)d_in[15];
    const float* Wd1     = (const float*)d_in[16];
    const float* bd1     = (const float*)d_in[17];
    const float* Wd2     = (const float*)d_in[18];
    const float* bd2     = (const float*)d_in[19];
    float* out = (float*)d_out;

    float *p_embW, *p_mask, *p_logacc, *p_hid, *p_ro, *p_hz, *p_sz, *p_hd, *p_pred;
    cudaGetSymbolAddress((void**)&p_embW,   g_embW);
    cudaGetSymbolAddress((void**)&p_mask,   g_maskbuf);
    cudaGetSymbolAddress((void**)&p_logacc, g_logacc);
    cudaGetSymbolAddress((void**)&p_hid,    g_hid);
    cudaGetSymbolAddress((void**)&p_ro,     g_ro);
    cudaGetSymbolAddress((void**)&p_hz,     g_hz);
    cudaGetSymbolAddress((void**)&p_sz,     g_sz);
    cudaGetSymbolAddress((void**)&p_hd,     g_hd);
    cudaGetSymbolAddress((void**)&p_pred,   g_pred);

    cudaFuncSetAttribute(lstm_seg_k, cudaFuncAttributeMaxDynamicSharedMemorySize,
                         SMEM_BYTES);

    // embW = embed @ Wx   (500 x 2048, K=512)
    sgemm_k<<<dim3(32, 8, 1), 256>>>(embed, 512, Wx, 2048, p_embW, 2048,
                                     500, 2048, 512, nullptr, 0);
    pack_embW_k<<<500, 512>>>(b_lstm);
    pack_Wh2_k<<<512, 256>>>(Wh);
    zero1_k<<<64, 256>>>(p_logacc, BB*TT);

    for (int seg = 0; seg < SS; seg++) {
        float* enc = out + OFF_ENCS + (size_t)seg * BTH;
        const float* mptr = (seg == 0) ? nullptr : p_mask;

        lstm_seg_k<<<NBLK, NTHR, SMEM_BYTES>>>(actions, mptr, enc);

        if (seg < SS - 1) {
            sgemm_k<<<dim3(8, 256, 1), 256>>>(enc, 512, Wb1, 512, p_hid, 512,
                                              16384, 512, 512, bb1, 1);
            rowdot_k<<<2048, 256>>>(p_hid, Wb2, bb2, out + OFF_LOGB + (size_t)seg*BB*TT);
            softmax_mask_k<<<64, 256>>>(out + OFF_LOGB + (size_t)seg*BB*TT,
                                        gumbel + (size_t)seg*BB*TT,
                                        out + OFF_SB + (size_t)seg*BB*TT,
                                        out + OFF_MASKS + (size_t)seg*BB*TT,
                                        p_mask, p_logacc);
        } else {
            onehot_k<<<64, 256>>>(lengths, out + OFF_SB + (size_t)seg*BB*TT);
        }

        readout_k<<<64, 512>>>(enc, out + OFF_SB + (size_t)seg*BB*TT, p_ro);

        sgemm_k<<<dim3(8, 1, 1), 256>>>(p_ro, 512, Wz1, 512, p_hz, 512,
                                        64, 512, 512, bz1, 1);
        sgemm_k<<<dim3(2, 1, 1), 256>>>(p_hz, 512, Wz2, 128,
                                        out + OFF_LZ + (size_t)seg*BB*2*LL, 128,
                                        64, 128, 512, bz2, 0);
        samplez_k<<<16, 256>>>(out + OFF_LZ + (size_t)seg*BB*2*LL,
                               eps_z + (size_t)seg*BB*LL,
                               out + OFF_SZ + (size_t)seg*BB*LL, p_sz);
        sgemm_k<<<dim3(8, 1, 1), 256>>>(p_sz, 64, Wd1, 512, p_hd, 512,
                                        64, 512, 64, bd1, 1);
        sgemm_k<<<dim3(8, 1, 1), 256>>>(p_hd, 512, Wd2, 500, p_pred, 500,
                                        64, 500, 512, bd2, 0);
        recs_k<<<32000, 256>>>(p_pred, out + OFF_RECS + (size_t)seg*(size_t)BB*TT*VV);
    }
}